// round 15
// baseline (speedup 1.0000x reference)
#include <cuda_runtime.h>
#include <cuda_fp16.h>
#include <cuda_fp8.h>
#include <math.h>

#define N_WORDS 100000
#define N_SAMPLES 65536
#define KNEG 10
#define NTERMS (KNEG + 1)
#define DIM 128
#define WARPS_PER_BLOCK 8
#define THREADS (WARPS_PER_BLOCK * 32)
#define SAMPLES_PER_WARP 8
#define SAMPLES_PER_BLOCK (WARPS_PER_BLOCK * SAMPLES_PER_WARP)   // 64
#define NUM_BATCHES (N_SAMPLES / SAMPLES_PER_BLOCK)              // 1024
#define LOSS_BLOCKS (NUM_BATCHES / 2)                            // 512, 2 batches each

// fp8(e4m3) copy of W_out, rebuilt every launch (12.8 MB scratch).
// Row layout PERMUTED: row r, uint4 #u dword #j = elements [32j+4u .. +4).
__device__ uint4         g_wout_f8[(size_t)N_WORDS * 8];
__device__ float         g_acc;      // zero at load; self-resets each run
__device__ unsigned int  g_count;    // arrival counter; self-resets each run

// fast log-sigmoid: min(x,0) - log(1 + exp(-|x|)), MUFU-based
__device__ __forceinline__ float log_sigmoid(float x) {
    float t = __expf(-fabsf(x));
    return fminf(x, 0.0f) - __logf(1.0f + t);
}

// sum across an aligned 4-lane group (replicated result)
__device__ __forceinline__ float group4_sum(float v) {
    v += __shfl_xor_sync(0xFFFFFFFFu, v, 1);
    v += __shfl_xor_sync(0xFFFFFFFFu, v, 2);
    return v;
}

__device__ __forceinline__ float warp_sum(float v) {
    v += __shfl_xor_sync(0xFFFFFFFFu, v, 16);
    v += __shfl_xor_sync(0xFFFFFFFFu, v, 8);
    v += __shfl_xor_sync(0xFFFFFFFFu, v, 4);
    v += __shfl_xor_sync(0xFFFFFFFFu, v, 2);
    v += __shfl_xor_sync(0xFFFFFFFFu, v, 1);
    return v;
}

__device__ __forceinline__ __half2 fp8x2_to_h2(unsigned short s) {
    __half2_raw r = __nv_cvt_fp8x2_to_halfraw2((__nv_fp8x2_storage_t)s, __NV_E4M3);
    return *reinterpret_cast<__half2*>(&r);
}

// ---- Kernel 1: W_out fp32 -> fp8 e4m3, permuted pack (8 threads per row) ----
#define CONV_THREADS 256
#define CONV_BLOCKS ((N_WORDS * 8) / CONV_THREADS)   // 3125

__global__ void __launch_bounds__(CONV_THREADS)
convert_wout_kernel(const float* __restrict__ W_out) {
    const int t   = blockIdx.x * CONV_THREADS + threadIdx.x;
    const int row = t >> 3;
    const int u   = t & 7;
    const float4* src = reinterpret_cast<const float4*>(W_out + (size_t)row * DIM);

    uint4 o;
    unsigned int* od = reinterpret_cast<unsigned int*>(&o);
#pragma unroll
    for (int j = 0; j < 4; j++) {
        float4 f = src[8 * j + u];        // coalesced 128B per load across group
        unsigned short lo = (unsigned short)
            __nv_cvt_float2_to_fp8x2(make_float2(f.x, f.y), __NV_SATFINITE, __NV_E4M3);
        unsigned short hi = (unsigned short)
            __nv_cvt_float2_to_fp8x2(make_float2(f.z, f.w), __NV_SATFINITE, __NV_E4M3);
        od[j] = (unsigned int)lo | ((unsigned int)hi << 16);
    }
    g_wout_f8[(size_t)row * 8 + u] = o;
}

// per-lane row dot: 32 a-halves vs 32 fp8 weights in two uint4
__device__ __forceinline__ float dot_row(const __half2* ahA, const __half2* ahB,
                                         const uint4& u0, const uint4& u1) {
    const unsigned int* d0 = reinterpret_cast<const unsigned int*>(&u0);
    const unsigned int* d1 = reinterpret_cast<const unsigned int*>(&u1);
    __half2 z = __float2half2_rn(0.0f);
    __half2 a0 = z, a1 = z, a2 = z, a3 = z;
#pragma unroll
    for (int j = 0; j < 4; j++) {
        unsigned int w0 = d0[j], w1 = d1[j];
        a0 = __hfma2(ahA[2 * j + 0], fp8x2_to_h2((unsigned short)(w0 & 0xFFFFu)), a0);
        a1 = __hfma2(ahA[2 * j + 1], fp8x2_to_h2((unsigned short)(w0 >> 16)),     a1);
        a2 = __hfma2(ahB[2 * j + 0], fp8x2_to_h2((unsigned short)(w1 & 0xFFFFu)), a2);
        a3 = __hfma2(ahB[2 * j + 1], fp8x2_to_h2((unsigned short)(w1 >> 16)),     a3);
    }
    __half2 s = __hadd2(__hadd2(a0, a1), __hadd2(a2, a3));
    float2 f = __half22float2(s);
    return f.x + f.y;
}

// one batch of R10-style compute; indices already in registers
__device__ __forceinline__ float batch_loss(int i_in, int i_out, const int* nidx,
                                            const float* __restrict__ W_in,
                                            int gl) {
    const float4* in_row = reinterpret_cast<const float4*>(
        W_in + (size_t)i_in * DIM);
    __half2 ahA[8], ahB[8];
#pragma unroll
    for (int j = 0; j < 4; j++) {
        float4 fA = in_row[8 * j + gl];
        float4 fB = in_row[8 * j + gl + 4];
        ahA[2 * j + 0] = __floats2half2_rn(fA.x, fA.y);
        ahA[2 * j + 1] = __floats2half2_rn(fA.z, fA.w);
        ahB[2 * j + 0] = __floats2half2_rn(fB.x, fB.y);
        ahB[2 * j + 1] = __floats2half2_rn(fB.z, fB.w);
    }

    float dpos;
    {
        const uint4* r = g_wout_f8 + (size_t)i_out * 8;
        dpos = dot_row(ahA, ahB, r[gl], r[gl + 4]);
    }
    dpos = group4_sum(dpos);
    float loss = log_sigmoid(dpos);

    float dneg[KNEG];
#pragma unroll
    for (int k = 0; k < KNEG; k++) {
        const uint4* r = g_wout_f8 + (size_t)nidx[k] * 8;
        dneg[k] = dot_row(ahA, ahB, r[gl], r[gl + 4]);
    }
#pragma unroll
    for (int k = 0; k < KNEG; k++) {
        float d = group4_sum(dneg[k]);
        loss += log_sigmoid(-d);
    }
    return loss;
}

// ---- Kernel 2: loss — 2 batches per block, index loads hoisted ----
__global__ void __launch_bounds__(THREADS)
skipgram_loss_kernel(const int* __restrict__ input_idx,
                     const int* __restrict__ output_idx,
                     const int* __restrict__ neg_idx,
                     const float* __restrict__ W_in,
                     float* __restrict__ out) {
    const int tid  = threadIdx.x;
    const int warp = tid >> 5;
    const int lane = tid & 31;
    const int grp  = lane >> 2;          // 0..7: sample slot within warp
    const int gl   = lane & 3;           // lane within 4-lane group
    const int sloc = warp * SAMPLES_PER_WARP + grp;   // 0..63

    const int nA = blockIdx.x * SAMPLES_PER_BLOCK + sloc;
    const int nB = (blockIdx.x + LOSS_BLOCKS) * SAMPLES_PER_BLOCK + sloc;

    // ---- hoist ALL index loads for both batches (independent LDGs) ----
    const int i_inA  = input_idx[nA];
    const int i_outA = output_idx[nA];
    const int i_inB  = input_idx[nB];
    const int i_outB = output_idx[nB];
    const int* nrowA = neg_idx + (size_t)nA * KNEG;
    const int* nrowB = neg_idx + (size_t)nB * KNEG;
    int nidxA[KNEG], nidxB[KNEG];
#pragma unroll
    for (int k = 0; k < KNEG; k++) nidxA[k] = nrowA[k];
#pragma unroll
    for (int k = 0; k < KNEG; k++) nidxB[k] = nrowB[k];

    // batch A compute fully covers batch B's index latency
    float loss_acc = batch_loss(i_inA, i_outA, nidxA, W_in, gl);
    loss_acc      += batch_loss(i_inB, i_outB, nidxB, W_in, gl);

    // ---- block reduce + global accumulate (last block finalizes) ----
    __shared__ float s[SAMPLES_PER_BLOCK];
    if (gl == 0) s[sloc] = loss_acc;
    __syncthreads();
    if (warp == 0) {
        float v = s[lane] + s[lane + 32];   // 64 partials -> 32
        v = warp_sum(v);
        if (lane == 0) {
            atomicAdd(&g_acc, v);
            __threadfence();
            unsigned int arrived = atomicAdd(&g_count, 1u);
            if (arrived == LOSS_BLOCKS - 1) {
                __threadfence();
                float total = atomicExch(&g_acc, 0.0f);   // read + reset
                out[0] = total * (1.0f / (float)N_SAMPLES);
                g_count = 0u;                              // reset for replay
                __threadfence();
            }
        }
    }
}

extern "C" void kernel_launch(void* const* d_in, const int* in_sizes, int n_in,
                              void* d_out, int out_size) {
    const int*   input_idx  = (const int*)d_in[0];
    const int*   output_idx = (const int*)d_in[1];
    const int*   neg_idx    = (const int*)d_in[2];
    const float* W_in       = (const float*)d_in[3];
    const float* W_out      = (const float*)d_in[4];
    float*       out        = (float*)d_out;

    convert_wout_kernel<<<CONV_BLOCKS, CONV_THREADS>>>(W_out);
    skipgram_loss_kernel<<<LOSS_BLOCKS, THREADS>>>(input_idx, output_idx, neg_idx,
                                                   W_in, out);
}

// round 16
// speedup vs baseline: 1.0531x; 1.0531x over previous
#include <cuda_runtime.h>
#include <cuda_fp16.h>
#include <cuda_fp8.h>
#include <math.h>

#define N_WORDS 100000
#define N_SAMPLES 65536
#define KNEG 10
#define NTERMS (KNEG + 1)
#define DIM 128
#define WARPS_PER_BLOCK 4
#define THREADS (WARPS_PER_BLOCK * 32)                           // 128
#define SAMPLES_PER_WARP 16
#define SAMPLES_PER_BLOCK (WARPS_PER_BLOCK * SAMPLES_PER_WARP)   // 64
#define NBLOCKS (N_SAMPLES / SAMPLES_PER_BLOCK)                  // 1024

// fp8(e4m3) copy of W_out, rebuilt every launch (12.8 MB scratch).
// Row layout PERMUTED: row r, uint4 #u dword #j = elements [32j+4u .. +4).
__device__ uint4         g_wout_f8[(size_t)N_WORDS * 8];
__device__ float         g_acc;      // zero at load; self-resets each run
__device__ unsigned int  g_count;    // arrival counter; self-resets each run

// fast log-sigmoid: min(x,0) - log(1 + exp(-|x|)), MUFU-based
__device__ __forceinline__ float log_sigmoid(float x) {
    float t = __expf(-fabsf(x));
    return fminf(x, 0.0f) - __logf(1.0f + t);
}

// sum across an aligned 2-lane group (replicated result)
__device__ __forceinline__ float group2_sum(float v) {
    v += __shfl_xor_sync(0xFFFFFFFFu, v, 1);
    return v;
}

__device__ __forceinline__ float warp_sum(float v) {
    v += __shfl_xor_sync(0xFFFFFFFFu, v, 16);
    v += __shfl_xor_sync(0xFFFFFFFFu, v, 8);
    v += __shfl_xor_sync(0xFFFFFFFFu, v, 4);
    v += __shfl_xor_sync(0xFFFFFFFFu, v, 2);
    v += __shfl_xor_sync(0xFFFFFFFFu, v, 1);
    return v;
}

__device__ __forceinline__ __half2 fp8x2_to_h2(unsigned short s) {
    __half2_raw r = __nv_cvt_fp8x2_to_halfraw2((__nv_fp8x2_storage_t)s, __NV_E4M3);
    return *reinterpret_cast<__half2*>(&r);
}

// ---- Kernel 1: W_out fp32 -> fp8 e4m3, permuted pack (8 threads per row) ----
#define CONV_THREADS 256
#define CONV_BLOCKS ((N_WORDS * 8) / CONV_THREADS)   // 3125

__global__ void __launch_bounds__(CONV_THREADS)
convert_wout_kernel(const float* __restrict__ W_out) {
    const int t   = blockIdx.x * CONV_THREADS + threadIdx.x;
    const int row = t >> 3;
    const int u   = t & 7;
    const float4* src = reinterpret_cast<const float4*>(W_out + (size_t)row * DIM);

    uint4 o;
    unsigned int* od = reinterpret_cast<unsigned int*>(&o);
#pragma unroll
    for (int j = 0; j < 4; j++) {
        float4 f = src[8 * j + u];        // coalesced 128B per load across group
        unsigned short lo = (unsigned short)
            __nv_cvt_float2_to_fp8x2(make_float2(f.x, f.y), __NV_SATFINITE, __NV_E4M3);
        unsigned short hi = (unsigned short)
            __nv_cvt_float2_to_fp8x2(make_float2(f.z, f.w), __NV_SATFINITE, __NV_E4M3);
        od[j] = (unsigned int)lo | ((unsigned int)hi << 16);
    }
    g_wout_f8[(size_t)row * 8 + u] = o;
}

// per-lane row dot: 64 a-halves (ah[4][8]) vs 64 fp8 weights (uint4 #gl+2i)
__device__ __forceinline__ float dot_row_g2(const __half2 ah[4][8],
                                            const uint4* __restrict__ rowp,
                                            int gl) {
    __half2 z = __float2half2_rn(0.0f);
    __half2 a0 = z, a1 = z, a2 = z, a3 = z;
#pragma unroll
    for (int i = 0; i < 4; i++) {
        uint4 u = rowp[gl + 2 * i];
        const unsigned int* ud = reinterpret_cast<const unsigned int*>(&u);
#pragma unroll
        for (int j = 0; j < 4; j++) {
            __half2 w0 = fp8x2_to_h2((unsigned short)(ud[j] & 0xFFFFu));
            __half2 w1 = fp8x2_to_h2((unsigned short)(ud[j] >> 16));
            if (j & 1) {
                a2 = __hfma2(ah[i][2 * j + 0], w0, a2);
                a3 = __hfma2(ah[i][2 * j + 1], w1, a3);
            } else {
                a0 = __hfma2(ah[i][2 * j + 0], w0, a0);
                a1 = __hfma2(ah[i][2 * j + 1], w1, a1);
            }
        }
    }
    __half2 s = __hadd2(__hadd2(a0, a1), __hadd2(a2, a3));
    float2 f = __half22float2(s);
    return f.x + f.y;
}

// ---- Kernel 2: loss — 2 lanes per sample, 16 samples per warp ----
__global__ void __launch_bounds__(THREADS)
skipgram_loss_kernel(const int* __restrict__ input_idx,
                     const int* __restrict__ output_idx,
                     const int* __restrict__ neg_idx,
                     const float* __restrict__ W_in,
                     float* __restrict__ out) {
    const int tid  = threadIdx.x;
    const int warp = tid >> 5;
    const int lane = tid & 31;
    const int grp  = lane >> 1;          // 0..15: sample slot within warp
    const int gl   = lane & 1;           // lane within 2-lane group
    const int sloc = warp * SAMPLES_PER_WARP + grp;   // 0..63
    const int n    = blockIdx.x * SAMPLES_PER_BLOCK + sloc;

    // scalar index loads (registers, broadcast within 2-lane group)
    const int i_in  = input_idx[n];
    const int i_out = output_idx[n];
    const int* nrow = neg_idx + (size_t)n * KNEG;
    int nidx[KNEG];
#pragma unroll
    for (int k = 0; k < KNEG; k++) nidx[k] = nrow[k];

    // input vector: lane gl covers uint4 slots u = gl + 2i (i=0..3);
    // a float4 8j+u matches uint4 #u dword #j. 16 LDG.128 per lane.
    const float4* in_row = reinterpret_cast<const float4*>(
        W_in + (size_t)i_in * DIM);
    __half2 ah[4][8];
#pragma unroll
    for (int i = 0; i < 4; i++) {
        const int u = gl + 2 * i;
#pragma unroll
        for (int j = 0; j < 4; j++) {
            float4 f = in_row[8 * j + u];
            ah[i][2 * j + 0] = __floats2half2_rn(f.x, f.y);
            ah[i][2 * j + 1] = __floats2half2_rn(f.z, f.w);
        }
    }

    // positive dot
    float dpos = dot_row_g2(ah, g_wout_f8 + (size_t)i_out * 8, gl);
    dpos = group2_sum(dpos);
    float loss = log_sigmoid(dpos);

    // negatives: flat unrolled, independent chains (ptxas batches loads)
    float dneg[KNEG];
#pragma unroll
    for (int k = 0; k < KNEG; k++)
        dneg[k] = dot_row_g2(ah, g_wout_f8 + (size_t)nidx[k] * 8, gl);
#pragma unroll
    for (int k = 0; k < KNEG; k++) {
        float d = group2_sum(dneg[k]);
        loss += log_sigmoid(-d);
    }

    // block reduce + global accumulate (last block finalizes + resets)
    __shared__ float s[SAMPLES_PER_BLOCK];
    if (gl == 0) s[sloc] = loss;
    __syncthreads();
    if (warp == 0) {
        float v = s[lane] + s[lane + 32];   // 64 partials -> 32
        v = warp_sum(v);
        if (lane == 0) {
            atomicAdd(&g_acc, v);
            __threadfence();
            unsigned int arrived = atomicAdd(&g_count, 1u);
            if (arrived == NBLOCKS - 1) {
                __threadfence();
                float total = atomicExch(&g_acc, 0.0f);   // read + reset
                out[0] = total * (1.0f / (float)N_SAMPLES);
                g_count = 0u;                              // reset for replay
                __threadfence();
            }
        }
    }
}

extern "C" void kernel_launch(void* const* d_in, const int* in_sizes, int n_in,
                              void* d_out, int out_size) {
    const int*   input_idx  = (const int*)d_in[0];
    const int*   output_idx = (const int*)d_in[1];
    const int*   neg_idx    = (const int*)d_in[2];
    const float* W_in       = (const float*)d_in[3];
    const float* W_out      = (const float*)d_in[4];
    float*       out        = (float*)d_out;

    convert_wout_kernel<<<CONV_BLOCKS, CONV_THREADS>>>(W_out);
    skipgram_loss_kernel<<<NBLOCKS, THREADS>>>(input_idx, output_idx, neg_idx,
                                               W_in, out);
}

// round 17
// speedup vs baseline: 1.0707x; 1.0168x over previous
#include <cuda_runtime.h>
#include <cuda_fp16.h>
#include <cuda_fp8.h>
#include <math.h>

#define N_WORDS 100000
#define N_SAMPLES 65536
#define KNEG 10
#define DIM 128
#define WARPS_PER_BLOCK 4
#define THREADS (WARPS_PER_BLOCK * 32)                           // 128
#define SAMPLES_PER_WARP 8
#define SAMPLES_PER_BLOCK (WARPS_PER_BLOCK * SAMPLES_PER_WARP)   // 32
#define NBLOCKS (N_SAMPLES / SAMPLES_PER_BLOCK)                  // 2048

// fp8(e4m3) copy of W_out, rebuilt every launch (12.8 MB scratch).
// Row layout PERMUTED: row r, uint4 #u dword #j = elements [32j+4u .. +4).
__device__ uint4         g_wout_f8[(size_t)N_WORDS * 8];
__device__ int           g_negT[KNEG * N_SAMPLES];   // neg_idx transposed [k][n]
__device__ float         g_acc;      // zero at load; self-resets each run
__device__ unsigned int  g_count;    // arrival counter; self-resets each run

// fast log-sigmoid: min(x,0) - log(1 + exp(-|x|)), MUFU-based
__device__ __forceinline__ float log_sigmoid(float x) {
    float t = __expf(-fabsf(x));
    return fminf(x, 0.0f) - __logf(1.0f + t);
}

// sum across an aligned 4-lane group (replicated result)
__device__ __forceinline__ float group4_sum(float v) {
    v += __shfl_xor_sync(0xFFFFFFFFu, v, 1);
    v += __shfl_xor_sync(0xFFFFFFFFu, v, 2);
    return v;
}

__device__ __forceinline__ float warp_sum(float v) {
    v += __shfl_xor_sync(0xFFFFFFFFu, v, 16);
    v += __shfl_xor_sync(0xFFFFFFFFu, v, 8);
    v += __shfl_xor_sync(0xFFFFFFFFu, v, 4);
    v += __shfl_xor_sync(0xFFFFFFFFu, v, 2);
    v += __shfl_xor_sync(0xFFFFFFFFu, v, 1);
    return v;
}

__device__ __forceinline__ __half2 fp8x2_to_h2(unsigned short s) {
    __half2_raw r = __nv_cvt_fp8x2_to_halfraw2((__nv_fp8x2_storage_t)s, __NV_E4M3);
    return *reinterpret_cast<__half2*>(&r);
}

// ---- Kernel 1: convert W_out -> fp8 (blocks 0..3124) + transpose neg_idx ----
#define CONV_THREADS 256
#define CONV_BLOCKS ((N_WORDS * 8) / CONV_THREADS)               // 3125
#define TR_BLOCKS (N_SAMPLES / CONV_THREADS)                     // 256
#define PRE_BLOCKS (CONV_BLOCKS + TR_BLOCKS)                     // 3381

__global__ void __launch_bounds__(CONV_THREADS)
prepare_kernel(const float* __restrict__ W_out,
               const int* __restrict__ neg_idx) {
    if (blockIdx.x < CONV_BLOCKS) {
        const int t   = blockIdx.x * CONV_THREADS + threadIdx.x;
        const int row = t >> 3;
        const int u   = t & 7;
        const float4* src = reinterpret_cast<const float4*>(W_out + (size_t)row * DIM);

        uint4 o;
        unsigned int* od = reinterpret_cast<unsigned int*>(&o);
#pragma unroll
        for (int j = 0; j < 4; j++) {
            float4 f = __ldcs(&src[8 * j + u]);   // evict-first: keep L2 for fp8
            unsigned short lo = (unsigned short)
                __nv_cvt_float2_to_fp8x2(make_float2(f.x, f.y), __NV_SATFINITE, __NV_E4M3);
            unsigned short hi = (unsigned short)
                __nv_cvt_float2_to_fp8x2(make_float2(f.z, f.w), __NV_SATFINITE, __NV_E4M3);
            od[j] = (unsigned int)lo | ((unsigned int)hi << 16);
        }
        g_wout_f8[(size_t)row * 8 + u] = o;
    } else {
        // transpose neg_idx [n][k] -> g_negT [k][n]; writes coalesced across n
        const int n = (blockIdx.x - CONV_BLOCKS) * CONV_THREADS + threadIdx.x;
        const int* src = neg_idx + (size_t)n * KNEG;
#pragma unroll
        for (int k = 0; k < KNEG; k++)
            g_negT[k * N_SAMPLES + n] = src[k];
    }
}

// per-lane row dot: 32 a-halves vs 32 fp8 weights in two uint4
__device__ __forceinline__ float dot_row(const __half2* ahA, const __half2* ahB,
                                         const uint4& u0, const uint4& u1) {
    const unsigned int* d0 = reinterpret_cast<const unsigned int*>(&u0);
    const unsigned int* d1 = reinterpret_cast<const unsigned int*>(&u1);
    __half2 z = __float2half2_rn(0.0f);
    __half2 a0 = z, a1 = z, a2 = z, a3 = z;
#pragma unroll
    for (int j = 0; j < 4; j++) {
        unsigned int w0 = d0[j], w1 = d1[j];
        a0 = __hfma2(ahA[2 * j + 0], fp8x2_to_h2((unsigned short)(w0 & 0xFFFFu)), a0);
        a1 = __hfma2(ahA[2 * j + 1], fp8x2_to_h2((unsigned short)(w0 >> 16)),     a1);
        a2 = __hfma2(ahB[2 * j + 0], fp8x2_to_h2((unsigned short)(w1 & 0xFFFFu)), a2);
        a3 = __hfma2(ahB[2 * j + 1], fp8x2_to_h2((unsigned short)(w1 >> 16)),     a3);
    }
    __half2 s = __hadd2(__hadd2(a0, a1), __hadd2(a2, a3));
    float2 f = __half22float2(s);
    return f.x + f.y;
}

// ---- Kernel 2: loss — R10 body, 4 lanes/sample, coalesced transposed idx ----
__global__ void __launch_bounds__(THREADS)
skipgram_loss_kernel(const int* __restrict__ input_idx,
                     const int* __restrict__ output_idx,
                     const float* __restrict__ W_in,
                     float* __restrict__ out) {
    const int tid  = threadIdx.x;
    const int warp = tid >> 5;
    const int lane = tid & 31;
    const int grp  = lane >> 2;          // 0..7: sample slot within warp
    const int gl   = lane & 3;           // lane within 4-lane group
    const int sloc = warp * SAMPLES_PER_WARP + grp;   // 0..31
    const int n    = blockIdx.x * SAMPLES_PER_BLOCK + sloc;

    // scalar index loads; neg idx from transposed layout (coalesced per k)
    const int i_in  = input_idx[n];
    const int i_out = output_idx[n];
    int nidx[KNEG];
#pragma unroll
    for (int k = 0; k < KNEG; k++) nidx[k] = g_negT[k * N_SAMPLES + n];

    // input vector: lane gl covers blocks matching uint4 #gl and #(gl+4)
    const float4* in_row = reinterpret_cast<const float4*>(
        W_in + (size_t)i_in * DIM);
    __half2 ahA[8], ahB[8];
#pragma unroll
    for (int j = 0; j < 4; j++) {
        float4 fA = in_row[8 * j + gl];
        float4 fB = in_row[8 * j + gl + 4];
        ahA[2 * j + 0] = __floats2half2_rn(fA.x, fA.y);
        ahA[2 * j + 1] = __floats2half2_rn(fA.z, fA.w);
        ahB[2 * j + 0] = __floats2half2_rn(fB.x, fB.y);
        ahB[2 * j + 1] = __floats2half2_rn(fB.z, fB.w);
    }

    // positive dot: lane loads uint4 gl and gl+4 of the row (32 B)
    float dpos;
    {
        const uint4* r = g_wout_f8 + (size_t)i_out * 8;
        dpos = dot_row(ahA, ahB, r[gl], r[gl + 4]);
    }
    dpos = group4_sum(dpos);
    float loss = log_sigmoid(dpos);

    // negatives: flat unrolled, independent chains (ptxas batches loads)
    float dneg[KNEG];
#pragma unroll
    for (int k = 0; k < KNEG; k++) {
        const uint4* r = g_wout_f8 + (size_t)nidx[k] * 8;
        dneg[k] = dot_row(ahA, ahB, r[gl], r[gl + 4]);
    }
#pragma unroll
    for (int k = 0; k < KNEG; k++) {
        float d = group4_sum(dneg[k]);
        loss += log_sigmoid(-d);
    }

    // block reduce + global accumulate (last block finalizes + resets)
    __shared__ float s[SAMPLES_PER_BLOCK];
    if (gl == 0) s[sloc] = loss;
    __syncthreads();
    if (warp == 0) {
        float v = s[lane];               // SAMPLES_PER_BLOCK == 32 exactly
        v = warp_sum(v);
        if (lane == 0) {
            atomicAdd(&g_acc, v);
            __threadfence();
            unsigned int arrived = atomicAdd(&g_count, 1u);
            if (arrived == NBLOCKS - 1) {
                __threadfence();
                float total = atomicExch(&g_acc, 0.0f);   // read + reset
                out[0] = total * (1.0f / (float)N_SAMPLES);
                g_count = 0u;                              // reset for replay
                __threadfence();
            }
        }
    }
}

extern "C" void kernel_launch(void* const* d_in, const int* in_sizes, int n_in,
                              void* d_out, int out_size) {
    const int*   input_idx  = (const int*)d_in[0];
    const int*   output_idx = (const int*)d_in[1];
    const int*   neg_idx    = (const int*)d_in[2];
    const float* W_in       = (const float*)d_in[3];
    const float* W_out      = (const float*)d_in[4];
    float*       out        = (float*)d_out;

    prepare_kernel<<<PRE_BLOCKS, CONV_THREADS>>>(W_out, neg_idx);
    skipgram_loss_kernel<<<NBLOCKS, THREADS>>>(input_idx, output_idx, W_in, out);
}